// round 1
// baseline (speedup 1.0000x reference)
#include <cuda_runtime.h>

#define C_S 384
#define C_Z 128
#define MAX_N 2048

// scratch for per-row projections (allocation-free rule: device globals)
__device__ float g_si[MAX_N];
__device__ float g_sj[MAX_N];

// ---------------------------------------------------------------------------
// Kernel 1: si[n] = dot(s[n,:], W[0:384]), sj[n] = dot(s[n,:], W[384:768])
// One warp per row n. s is tiny (1.5 MB) — this kernel is noise (<3 us).
// ---------------------------------------------------------------------------
__global__ void precompute_sisj_kernel(const float* __restrict__ s,
                                       const float* __restrict__ W,
                                       int N) {
    int warp = (blockIdx.x * blockDim.x + threadIdx.x) >> 5;
    int lane = threadIdx.x & 31;
    if (warp >= N) return;
    const float* srow = s + (size_t)warp * C_S;
    float ai = 0.f, aj = 0.f;
#pragma unroll
    for (int k = lane; k < C_S; k += 32) {
        float v = __ldg(srow + k);
        ai += v * __ldg(W + k);
        aj += v * __ldg(W + C_S + k);
    }
#pragma unroll
    for (int off = 16; off; off >>= 1) {
        ai += __shfl_xor_sync(0xFFFFFFFFu, ai, off);
        aj += __shfl_xor_sync(0xFFFFFFFFu, aj, off);
    }
    if (lane == 0) {
        g_si[warp] = ai;
        g_sj[warp] = aj;
    }
}

// ---------------------------------------------------------------------------
// Kernel 2: out[n*N + m] = g_si[n] + g_sj[m] + dot(z[n,m,:], Wz) + b
// Warp handles 8 consecutive m (same n). Each lane loads one float4 of the
// 512-byte z-row -> fully coalesced 512B per row, 8 independent loads in
// flight per warp (MLP=8). Butterfly reduce, lane 0 writes 2x float4.
// ---------------------------------------------------------------------------
__global__ __launch_bounds__(256) void contact_main_kernel(
    const float* __restrict__ z,
    const float* __restrict__ W,
    const float* __restrict__ bias,
    float* __restrict__ out,
    int N) {
    int warp = (blockIdx.x * blockDim.x + threadIdx.x) >> 5;
    int lane = threadIdx.x & 31;

    long long base = (long long)warp * 8;
    long long total = (long long)N * (long long)N;
    if (base >= total) return;

    int n  = (int)(base / N);
    int m0 = (int)(base - (long long)n * N);   // N % 8 == 0 -> all 8 share n

    // Wz = W[768:896], resident in L1/L2 after first touch
    const float4* wz4 = (const float4*)(W + 2 * C_S);
    float4 wz = __ldg(wz4 + lane);
    float b0  = __ldg(bias);

    const float4* z4 = (const float4*)z;
    size_t row0 = ((size_t)n * N + m0) * (C_Z / 4);  // float4 index of row m0

    float a0, a1, a2, a3, a4, a5, a6, a7;
    {
        float4 v0 = __ldg(z4 + row0 + 0 * (C_Z / 4) + lane);
        float4 v1 = __ldg(z4 + row0 + 1 * (C_Z / 4) + lane);
        float4 v2 = __ldg(z4 + row0 + 2 * (C_Z / 4) + lane);
        float4 v3 = __ldg(z4 + row0 + 3 * (C_Z / 4) + lane);
        float4 v4 = __ldg(z4 + row0 + 4 * (C_Z / 4) + lane);
        float4 v5 = __ldg(z4 + row0 + 5 * (C_Z / 4) + lane);
        float4 v6 = __ldg(z4 + row0 + 6 * (C_Z / 4) + lane);
        float4 v7 = __ldg(z4 + row0 + 7 * (C_Z / 4) + lane);
        a0 = v0.x * wz.x + v0.y * wz.y + v0.z * wz.z + v0.w * wz.w;
        a1 = v1.x * wz.x + v1.y * wz.y + v1.z * wz.z + v1.w * wz.w;
        a2 = v2.x * wz.x + v2.y * wz.y + v2.z * wz.z + v2.w * wz.w;
        a3 = v3.x * wz.x + v3.y * wz.y + v3.z * wz.z + v3.w * wz.w;
        a4 = v4.x * wz.x + v4.y * wz.y + v4.z * wz.z + v4.w * wz.w;
        a5 = v5.x * wz.x + v5.y * wz.y + v5.z * wz.z + v5.w * wz.w;
        a6 = v6.x * wz.x + v6.y * wz.y + v6.z * wz.z + v6.w * wz.w;
        a7 = v7.x * wz.x + v7.y * wz.y + v7.z * wz.z + v7.w * wz.w;
    }

#pragma unroll
    for (int off = 16; off; off >>= 1) {
        a0 += __shfl_xor_sync(0xFFFFFFFFu, a0, off);
        a1 += __shfl_xor_sync(0xFFFFFFFFu, a1, off);
        a2 += __shfl_xor_sync(0xFFFFFFFFu, a2, off);
        a3 += __shfl_xor_sync(0xFFFFFFFFu, a3, off);
        a4 += __shfl_xor_sync(0xFFFFFFFFu, a4, off);
        a5 += __shfl_xor_sync(0xFFFFFFFFu, a5, off);
        a6 += __shfl_xor_sync(0xFFFFFFFFu, a6, off);
        a7 += __shfl_xor_sync(0xFFFFFFFFu, a7, off);
    }

    if (lane == 0) {
        float sn = g_si[n] + b0;
        float4 r0, r1;
        r0.x = a0 + sn + g_sj[m0 + 0];
        r0.y = a1 + sn + g_sj[m0 + 1];
        r0.z = a2 + sn + g_sj[m0 + 2];
        r0.w = a3 + sn + g_sj[m0 + 3];
        r1.x = a4 + sn + g_sj[m0 + 4];
        r1.y = a5 + sn + g_sj[m0 + 5];
        r1.z = a6 + sn + g_sj[m0 + 6];
        r1.w = a7 + sn + g_sj[m0 + 7];
        float4* o4 = (float4*)(out + base);
        o4[0] = r0;
        o4[1] = r1;
    }
}

extern "C" void kernel_launch(void* const* d_in, const int* in_sizes, int n_in,
                              void* d_out, int out_size) {
    const float* s    = (const float*)d_in[0];   // (1, N, 384)
    const float* z    = (const float*)d_in[1];   // (1, N, N, 128)
    const float* W    = (const float*)d_in[2];   // (1, 896)
    const float* bias = (const float*)d_in[3];   // (1,)
    float* out = (float*)d_out;                  // (1, N, N, 1)

    int N = in_sizes[0] / C_S;                   // B=1

    // Kernel 1: one warp per row, 256 threads/block
    {
        int warps = N;
        int threads = 256;
        int blocks = (warps * 32 + threads - 1) / threads;
        precompute_sisj_kernel<<<blocks, threads>>>(s, W, N);
    }

    // Kernel 2: one warp per 8 outputs
    {
        long long total = (long long)N * (long long)N;
        long long warps = (total + 7) / 8;
        int threads = 256;
        long long blocks = (warps * 32 + threads - 1) / threads;
        contact_main_kernel<<<(unsigned)blocks, threads>>>(z, W, bias, out, N);
    }
}